// round 10
// baseline (speedup 1.0000x reference)
#include <cuda_runtime.h>
#include <cstdint>

// B=16, N=M=2048, D=V=128 fp32, causal; key padding zeroes the last pad K rows.
namespace {
constexpr int B  = 16, Nq = 2048, Mk = 2048, Dh = 128, Vw = 128;
constexpr int BR = 128;   // query rows per CTA
constexpr int BC = 64;    // key cols per tile
constexpr int NT = 256;   // 8 warps; warp w owns rows [w*16, w*16+16)
constexpr float SC2 = 0.12754245778372862f;          // (1/sqrt(128)) * log2(e)

// smem strides (32-bit words), conflict-free fragment access:
//  K b-frag bank = 4g+tig (stride 132), V b-frag bank = 8tig+g (stride 136),
//  P a-frag bank = 4g+tig (stride 68).
constexpr int KS_STR = 132, VS_STR = 136, PS_STR = 68;
constexpr int TILE_F = BC * KS_STR + BC * VS_STR;   // 17152 floats per KV buffer
constexpr int OFF_P  = 2 * TILE_F;                  // 34304
constexpr int SMEM_FLOATS = OFF_P + BR * PS_STR;    // 43008 -> 172032 B
}

__device__ __forceinline__ uint32_t tf32r(float x) {
    uint32_t r; asm("cvt.rna.tf32.f32 %0, %1;" : "=r"(r) : "f"(x)); return r;
}

// D = A(16x8, tf32, row) * B(8x8, tf32, col) + D  (fp32 accum), in place.
__device__ __forceinline__ void mma8(float* c, const uint32_t* a,
                                     uint32_t b0, uint32_t b1) {
    asm volatile(
        "mma.sync.aligned.m16n8k8.row.col.f32.tf32.tf32.f32 "
        "{%0,%1,%2,%3}, {%4,%5,%6,%7}, {%8,%9}, {%0,%1,%2,%3};"
        : "+f"(c[0]), "+f"(c[1]), "+f"(c[2]), "+f"(c[3])
        : "r"(a[0]), "r"(a[1]), "r"(a[2]), "r"(a[3]), "r"(b0), "r"(b1));
}

__global__ __launch_bounds__(NT, 1)
void fattn_mma(const float* __restrict__ Qg, const float* __restrict__ Kg,
               const float* __restrict__ Vg, const int* __restrict__ padg,
               float* __restrict__ Og)
{
    extern __shared__ float smf[];
    uint32_t* smU = reinterpret_cast<uint32_t*>(smf);

    const int t = threadIdx.x, w = t >> 5, lane = t & 31;
    const int g = lane >> 2, tig = lane & 3;           // quad layout
    const int b = blockIdx.x & 15;
    const int qtile = 15 - (blockIdx.x >> 4);          // heavy tiles first
    const int q0 = qtile * BR;
    const int valid_m = Mk - padg[b];
    const int rloc = w * 16 + g;                       // CTA-local row of frag row0
    const int qg0 = q0 + rloc, qg1 = qg0 + 8;          // global query rows

    const float* Kb = Kg + (size_t)b * Mk * Dh;
    const float* Vb = Vg + (size_t)b * Mk * Vw;

    // prefetch tile kt into KV buffer bsel (LDG -> tf32 -> STS)
    auto load_tile = [&](int kt, int bsel) {
        const int m0 = kt * BC;
        uint32_t* bK = smU + bsel * TILE_F;
        uint32_t* bV = bK + BC * KS_STR;
        #pragma unroll
        for (int i = 0; i < 8; ++i) {
            const int idx = t + i * NT, r = idx >> 5, f = idx & 31;
            const int gm = m0 + r;
            float4 v = make_float4(0.f, 0.f, 0.f, 0.f);
            if (gm < valid_m)
                v = reinterpret_cast<const float4*>(Kb + (size_t)gm * Dh)[f];
            *reinterpret_cast<uint4*>(bK + r * KS_STR + 4 * f) =
                make_uint4(tf32r(v.x), tf32r(v.y), tf32r(v.z), tf32r(v.w));
        }
        #pragma unroll
        for (int i = 0; i < 8; ++i) {
            const int idx = t + i * NT, r = idx >> 5, f = idx & 31;
            float4 v = reinterpret_cast<const float4*>(
                Vb + (size_t)(m0 + r) * Vw)[f];
            *reinterpret_cast<uint4*>(bV + r * VS_STR + 4 * f) =
                make_uint4(tf32r(v.x), tf32r(v.y), tf32r(v.z), tf32r(v.w));
        }
    };

    // ---- Q A-fragments (tf32), register-resident for whole kernel ----
    uint32_t qa[16][4];
    {
        const float* Q0 = Qg + ((size_t)b * Nq + qg0) * Dh;
        const float* Q1 = Q0 + 8 * (size_t)Dh;
        #pragma unroll
        for (int s = 0; s < 16; ++s) {
            qa[s][0] = tf32r(Q0[8 * s + tig]);
            qa[s][1] = tf32r(Q1[8 * s + tig]);
            qa[s][2] = tf32r(Q0[8 * s + tig + 4]);
            qa[s][3] = tf32r(Q1[8 * s + tig + 4]);
        }
    }

    float o[16][4];
    #pragma unroll
    for (int nt = 0; nt < 16; ++nt)
        o[nt][0] = o[nt][1] = o[nt][2] = o[nt][3] = 0.f;
    float m0r = -1e30f, m1r = -1e30f, l0 = 0.f, l1 = 0.f;

    const int kt_end = 2 * qtile + 2;
    load_tile(0, 0);

    #pragma unroll 1
    for (int kt = 0; kt < kt_end; ++kt) {
        const int m0 = kt * BC;
        __syncthreads();   // tile kt STS visible; prev compute done with buf (kt+1)&1

        if (kt + 1 < kt_end) load_tile(kt + 1, (kt + 1) & 1);

        const uint32_t* bK = smU + (kt & 1) * TILE_F;
        const uint32_t* bV = bK + BC * KS_STR;

        // ---- S = Q K^T : 8 n-tiles x 16 k-steps of m16n8k8 ----
        float sc[8][4];
        #pragma unroll
        for (int nt = 0; nt < 8; ++nt)
            sc[nt][0] = sc[nt][1] = sc[nt][2] = sc[nt][3] = 0.f;
        #pragma unroll
        for (int s = 0; s < 16; ++s) {
            #pragma unroll
            for (int nt = 0; nt < 8; ++nt) {
                const uint32_t* kp = bK + (8 * nt + g) * KS_STR + 8 * s + tig;
                mma8(sc[nt], qa[s], kp[0], kp[4]);
            }
        }

        // ---- scale (exp2 domain) + causal mask + online softmax ----
        const bool needMask = (kt >= 2 * qtile);
        float mx0 = -1e30f, mx1 = -1e30f;
        #pragma unroll
        for (int nt = 0; nt < 8; ++nt) {
            const int c0 = m0 + 8 * nt + 2 * tig;
            float x0 = sc[nt][0] * SC2, x1 = sc[nt][1] * SC2;
            float x2 = sc[nt][2] * SC2, x3 = sc[nt][3] * SC2;
            if (needMask) {
                if (c0     > qg0) x0 = -1e30f;
                if (c0 + 1 > qg0) x1 = -1e30f;
                if (c0     > qg1) x2 = -1e30f;
                if (c0 + 1 > qg1) x3 = -1e30f;
            }
            sc[nt][0] = x0; sc[nt][1] = x1; sc[nt][2] = x2; sc[nt][3] = x3;
            mx0 = fmaxf(mx0, fmaxf(x0, x1));
            mx1 = fmaxf(mx1, fmaxf(x2, x3));
        }
        mx0 = fmaxf(mx0, __shfl_xor_sync(0xffffffffu, mx0, 1));
        mx0 = fmaxf(mx0, __shfl_xor_sync(0xffffffffu, mx0, 2));
        mx1 = fmaxf(mx1, __shfl_xor_sync(0xffffffffu, mx1, 1));
        mx1 = fmaxf(mx1, __shfl_xor_sync(0xffffffffu, mx1, 2));
        const float mn0 = fmaxf(m0r, mx0), mn1 = fmaxf(m1r, mx1);
        const float a0 = exp2f(m0r - mn0), a1 = exp2f(m1r - mn1);
        m0r = mn0; m1r = mn1;

        float ls0 = 0.f, ls1 = 0.f;
        #pragma unroll
        for (int nt = 0; nt < 8; ++nt) {
            const float p0 = exp2f(sc[nt][0] - mn0);
            const float p1 = exp2f(sc[nt][1] - mn0);
            const float p2 = exp2f(sc[nt][2] - mn1);
            const float p3 = exp2f(sc[nt][3] - mn1);
            ls0 += p0 + p1; ls1 += p2 + p3;
            *reinterpret_cast<uint2*>(
                smU + OFF_P + rloc * PS_STR + 8 * nt + 2 * tig) =
                make_uint2(tf32r(p0), tf32r(p1));
            *reinterpret_cast<uint2*>(
                smU + OFF_P + (rloc + 8) * PS_STR + 8 * nt + 2 * tig) =
                make_uint2(tf32r(p2), tf32r(p3));
        }
        ls0 += __shfl_xor_sync(0xffffffffu, ls0, 1);
        ls0 += __shfl_xor_sync(0xffffffffu, ls0, 2);
        ls1 += __shfl_xor_sync(0xffffffffu, ls1, 1);
        ls1 += __shfl_xor_sync(0xffffffffu, ls1, 2);
        l0 = l0 * a0 + ls0;
        l1 = l1 * a1 + ls1;

        #pragma unroll
        for (int nt = 0; nt < 16; ++nt) {
            o[nt][0] *= a0; o[nt][1] *= a0;
            o[nt][2] *= a1; o[nt][3] *= a1;
        }
        __syncwarp();   // P rows are warp-private: writer->reader lane exchange

        // ---- O += P V : 16 n-tiles x 8 k-steps ----
        #pragma unroll
        for (int s = 0; s < 8; ++s) {
            const uint32_t* pp = smU + OFF_P + rloc * PS_STR + 8 * s + tig;
            const uint32_t pa[4] = { pp[0], pp[8 * PS_STR],
                                     pp[4], pp[8 * PS_STR + 4] };
            #pragma unroll
            for (int nt = 0; nt < 16; ++nt) {
                const uint32_t* vp = bV + (8 * s + tig) * VS_STR + 8 * nt + g;
                mma8(o[nt], pa, vp[0], vp[4 * VS_STR]);
            }
        }
    }

    // ---- epilogue: normalize, store ----
    const float i0 = 1.f / l0, i1 = 1.f / l1;
    float* O0 = Og + ((size_t)b * Nq + qg0) * Vw;
    float* O1 = O0 + 8 * (size_t)Vw;
    #pragma unroll
    for (int nt = 0; nt < 16; ++nt) {
        const int c = 8 * nt + 2 * tig;
        *reinterpret_cast<float2*>(O0 + c) =
            make_float2(o[nt][0] * i0, o[nt][1] * i0);
        *reinterpret_cast<float2*>(O1 + c) =
            make_float2(o[nt][2] * i1, o[nt][3] * i1);
    }
}

extern "C" void kernel_launch(void* const* d_in, const int* in_sizes, int n_in,
                              void* d_out, int out_size)
{
    const float* Q   = (const float*)d_in[0];
    const float* K   = (const float*)d_in[1];
    const float* V   = (const float*)d_in[2];
    const int*   pad = (const int*)d_in[3];
    float*       O   = (float*)d_out;
    (void)in_sizes; (void)n_in; (void)out_size;

    const size_t smem = SMEM_FLOATS * sizeof(float);   // 172032 B
    static const bool once = [&]() {
        cudaFuncSetAttribute(fattn_mma,
                             cudaFuncAttributeMaxDynamicSharedMemorySize,
                             (int)smem);
        return true;
    }();
    (void)once;

    fattn_mma<<<B * (Nq / BR), NT, smem>>>(Q, K, V, pad, O);
}

// round 11
// speedup vs baseline: 1.0084x; 1.0084x over previous
#include <cuda_runtime.h>
#include <cstdint>

// B=16, N=M=2048, D=V=128 fp32, causal; key padding zeroes the last pad K rows.
namespace {
constexpr int B  = 16, Nq = 2048, Mk = 2048, Dh = 128, Vw = 128;
constexpr int BR = 128;   // query rows per CTA
constexpr int BC = 64;    // key cols per tile
constexpr int NT = 256;   // 8 warps; warp w owns rows [w*16, w*16+16)
constexpr float SC2 = 0.12754245778372862f;          // (1/sqrt(128)) * log2(e)

// smem strides (32-bit words), conflict-free fragment access:
//  K b-frag bank = 4g+tig (stride 132), V b-frag bank = 8tig+g (stride 136),
//  P a-frag bank = 4g+tig (stride 68).
constexpr int KS_STR = 132, VS_STR = 136, PS_STR = 68;
constexpr int TILE_F = BC * KS_STR + BC * VS_STR;   // 17152 floats per KV buffer
constexpr int OFF_P  = 2 * TILE_F;                  // 34304
constexpr int SMEM_FLOATS = OFF_P + BR * PS_STR;    // 43008 -> 172032 B
}

__device__ __forceinline__ uint32_t tf32r(float x) {
    uint32_t r; asm("cvt.rna.tf32.f32 %0, %1;" : "=r"(r) : "f"(x)); return r;
}

// D = A(16x8, tf32, row) * B(8x8, tf32, col) + D  (fp32 accum), in place.
__device__ __forceinline__ void mma8(float* c, const uint32_t* a,
                                     uint32_t b0, uint32_t b1) {
    asm volatile(
        "mma.sync.aligned.m16n8k8.row.col.f32.tf32.tf32.f32 "
        "{%0,%1,%2,%3}, {%4,%5,%6,%7}, {%8,%9}, {%0,%1,%2,%3};"
        : "+f"(c[0]), "+f"(c[1]), "+f"(c[2]), "+f"(c[3])
        : "r"(a[0]), "r"(a[1]), "r"(a[2]), "r"(a[3]), "r"(b0), "r"(b1));
}

__global__ __launch_bounds__(NT, 1)
void fattn_mma(const float* __restrict__ Qg, const float* __restrict__ Kg,
               const float* __restrict__ Vg, const int* __restrict__ padg,
               float* __restrict__ Og)
{
    extern __shared__ float smf[];
    uint32_t* smU = reinterpret_cast<uint32_t*>(smf);

    const int t = threadIdx.x, w = t >> 5, lane = t & 31;
    const int g = lane >> 2, tig = lane & 3;           // quad layout
    const int b = blockIdx.x & 15;
    const int qtile = 15 - (blockIdx.x >> 4);          // heavy tiles first
    const int q0 = qtile * BR;
    const int valid_m = Mk - padg[b];
    const int rloc = w * 16 + g;                       // CTA-local row of frag row0
    const int qg0 = q0 + rloc, qg1 = qg0 + 8;          // global query rows

    const float* Kb = Kg + (size_t)b * Mk * Dh;
    const float* Vb = Vg + (size_t)b * Mk * Vw;

    // prefetch tile kt into KV buffer bsel (LDG -> tf32 -> STS)
    auto load_tile = [&](int kt, int bsel) {
        const int m0 = kt * BC;
        uint32_t* bK = smU + bsel * TILE_F;
        uint32_t* bV = bK + BC * KS_STR;
        #pragma unroll
        for (int i = 0; i < 8; ++i) {
            const int idx = t + i * NT, r = idx >> 5, f = idx & 31;
            const int gm = m0 + r;
            float4 v = make_float4(0.f, 0.f, 0.f, 0.f);
            if (gm < valid_m)
                v = reinterpret_cast<const float4*>(Kb + (size_t)gm * Dh)[f];
            *reinterpret_cast<uint4*>(bK + r * KS_STR + 4 * f) =
                make_uint4(tf32r(v.x), tf32r(v.y), tf32r(v.z), tf32r(v.w));
        }
        #pragma unroll
        for (int i = 0; i < 8; ++i) {
            const int idx = t + i * NT, r = idx >> 5, f = idx & 31;
            float4 v = reinterpret_cast<const float4*>(
                Vb + (size_t)(m0 + r) * Vw)[f];
            *reinterpret_cast<uint4*>(bV + r * VS_STR + 4 * f) =
                make_uint4(tf32r(v.x), tf32r(v.y), tf32r(v.z), tf32r(v.w));
        }
    };

    // ---- Q A-fragments (tf32), register-resident for whole kernel ----
    uint32_t qa[16][4];
    {
        const float* Q0 = Qg + ((size_t)b * Nq + qg0) * Dh;
        const float* Q1 = Q0 + 8 * (size_t)Dh;
        #pragma unroll
        for (int s = 0; s < 16; ++s) {
            qa[s][0] = tf32r(Q0[8 * s + tig]);
            qa[s][1] = tf32r(Q1[8 * s + tig]);
            qa[s][2] = tf32r(Q0[8 * s + tig + 4]);
            qa[s][3] = tf32r(Q1[8 * s + tig + 4]);
        }
    }

    float o[16][4];
    #pragma unroll
    for (int nt = 0; nt < 16; ++nt)
        o[nt][0] = o[nt][1] = o[nt][2] = o[nt][3] = 0.f;
    float m0r = -1e30f, m1r = -1e30f, l0 = 0.f, l1 = 0.f;

    const int kt_end = 2 * qtile + 2;
    load_tile(0, 0);

    #pragma unroll 1
    for (int kt = 0; kt < kt_end; ++kt) {
        const int m0 = kt * BC;
        __syncthreads();   // tile kt STS visible; prev compute done with buf (kt+1)&1

        if (kt + 1 < kt_end) load_tile(kt + 1, (kt + 1) & 1);

        const uint32_t* bK = smU + (kt & 1) * TILE_F;
        const uint32_t* bV = bK + BC * KS_STR;

        // ---- S = Q K^T : 8 n-tiles x 16 k-steps of m16n8k8 ----
        float sc[8][4];
        #pragma unroll
        for (int nt = 0; nt < 8; ++nt)
            sc[nt][0] = sc[nt][1] = sc[nt][2] = sc[nt][3] = 0.f;
        #pragma unroll
        for (int s = 0; s < 16; ++s) {
            #pragma unroll
            for (int nt = 0; nt < 8; ++nt) {
                const uint32_t* kp = bK + (8 * nt + g) * KS_STR + 8 * s + tig;
                mma8(sc[nt], qa[s], kp[0], kp[4]);
            }
        }

        // ---- scale (exp2 domain) + causal mask + online softmax ----
        const bool needMask = (kt >= 2 * qtile);
        float mx0 = -1e30f, mx1 = -1e30f;
        #pragma unroll
        for (int nt = 0; nt < 8; ++nt) {
            const int c0 = m0 + 8 * nt + 2 * tig;
            float x0 = sc[nt][0] * SC2, x1 = sc[nt][1] * SC2;
            float x2 = sc[nt][2] * SC2, x3 = sc[nt][3] * SC2;
            if (needMask) {
                if (c0     > qg0) x0 = -1e30f;
                if (c0 + 1 > qg0) x1 = -1e30f;
                if (c0     > qg1) x2 = -1e30f;
                if (c0 + 1 > qg1) x3 = -1e30f;
            }
            sc[nt][0] = x0; sc[nt][1] = x1; sc[nt][2] = x2; sc[nt][3] = x3;
            mx0 = fmaxf(mx0, fmaxf(x0, x1));
            mx1 = fmaxf(mx1, fmaxf(x2, x3));
        }
        mx0 = fmaxf(mx0, __shfl_xor_sync(0xffffffffu, mx0, 1));
        mx0 = fmaxf(mx0, __shfl_xor_sync(0xffffffffu, mx0, 2));
        mx1 = fmaxf(mx1, __shfl_xor_sync(0xffffffffu, mx1, 1));
        mx1 = fmaxf(mx1, __shfl_xor_sync(0xffffffffu, mx1, 2));
        const float mn0 = fmaxf(m0r, mx0), mn1 = fmaxf(m1r, mx1);
        const float a0 = exp2f(m0r - mn0), a1 = exp2f(m1r - mn1);
        m0r = mn0; m1r = mn1;

        float ls0 = 0.f, ls1 = 0.f;
        #pragma unroll
        for (int nt = 0; nt < 8; ++nt) {
            const float p0 = exp2f(sc[nt][0] - mn0);
            const float p1 = exp2f(sc[nt][1] - mn0);
            const float p2 = exp2f(sc[nt][2] - mn1);
            const float p3 = exp2f(sc[nt][3] - mn1);
            ls0 += p0 + p1; ls1 += p2 + p3;
            *reinterpret_cast<uint2*>(
                smU + OFF_P + rloc * PS_STR + 8 * nt + 2 * tig) =
                make_uint2(tf32r(p0), tf32r(p1));
            *reinterpret_cast<uint2*>(
                smU + OFF_P + (rloc + 8) * PS_STR + 8 * nt + 2 * tig) =
                make_uint2(tf32r(p2), tf32r(p3));
        }
        ls0 += __shfl_xor_sync(0xffffffffu, ls0, 1);
        ls0 += __shfl_xor_sync(0xffffffffu, ls0, 2);
        ls1 += __shfl_xor_sync(0xffffffffu, ls1, 1);
        ls1 += __shfl_xor_sync(0xffffffffu, ls1, 2);
        l0 = l0 * a0 + ls0;
        l1 = l1 * a1 + ls1;

        #pragma unroll
        for (int nt = 0; nt < 16; ++nt) {
            o[nt][0] *= a0; o[nt][1] *= a0;
            o[nt][2] *= a1; o[nt][3] *= a1;
        }
        __syncwarp();   // P rows are warp-private: writer->reader lane exchange

        // ---- O += P V : 16 n-tiles x 8 k-steps ----
        #pragma unroll
        for (int s = 0; s < 8; ++s) {
            const uint32_t* pp = smU + OFF_P + rloc * PS_STR + 8 * s + tig;
            const uint32_t pa[4] = { pp[0], pp[8 * PS_STR],
                                     pp[4], pp[8 * PS_STR + 4] };
            #pragma unroll
            for (int nt = 0; nt < 16; ++nt) {
                const uint32_t* vp = bV + (8 * s + tig) * VS_STR + 8 * nt + g;
                mma8(o[nt], pa, vp[0], vp[4 * VS_STR]);
            }
        }
    }

    // ---- epilogue: normalize, store ----
    const float i0 = 1.f / l0, i1 = 1.f / l1;
    float* O0 = Og + ((size_t)b * Nq + qg0) * Vw;
    float* O1 = O0 + 8 * (size_t)Vw;
    #pragma unroll
    for (int nt = 0; nt < 16; ++nt) {
        const int c = 8 * nt + 2 * tig;
        *reinterpret_cast<float2*>(O0 + c) =
            make_float2(o[nt][0] * i0, o[nt][1] * i0);
        *reinterpret_cast<float2*>(O1 + c) =
            make_float2(o[nt][2] * i1, o[nt][3] * i1);
    }
}

extern "C" void kernel_launch(void* const* d_in, const int* in_sizes, int n_in,
                              void* d_out, int out_size)
{
    const float* Q   = (const float*)d_in[0];
    const float* K   = (const float*)d_in[1];
    const float* V   = (const float*)d_in[2];
    const int*   pad = (const int*)d_in[3];
    float*       O   = (float*)d_out;
    (void)in_sizes; (void)n_in; (void)out_size;

    const size_t smem = SMEM_FLOATS * sizeof(float);   // 172032 B
    static const bool once = [&]() {
        cudaFuncSetAttribute(fattn_mma,
                             cudaFuncAttributeMaxDynamicSharedMemorySize,
                             (int)smem);
        return true;
    }();
    (void)once;

    fattn_mma<<<B * (Nq / BR), NT, smem>>>(Q, K, V, pad, O);
}